// round 15
// baseline (speedup 1.0000x reference)
#include <cuda_runtime.h>

// out[row, e] = cos(x[row, 1]) * W_dec[e] + b_dec[e]
// x: (32768, 1024) fp32 ; W_dec,b_dec: (1024,) ; out: (32768, 1024)
// FINAL (R4 champion config). Pinned at the DRAM write ceiling:
// ~5.7 TB/s effective (134 MB output / ~23.7us), 71% of 8 TB/s spec.
// Store-issue and LTS both have ~2x headroom; run-to-run noise ~0.6us
// (identical source measured 23.42 and 24.03 in different rounds).
// Rejected with measurements: v8 stores (+2.4us), persistent grid (+3us),
// write-back stores (+5us), hybrid wb/cs (+1.1us), evict_last pinning
// (+1.2us), TMA bulk store (+4.5us), shfl broadcast (tie), store burst (+0.6us).
// Config: 8192 blocks x 256 threads, 4 rows/block (7 waves, ~1% tail),
// smem cos broadcast, register-resident W/b, float4 evict-first stores.

#define EMBED 1024
#define VEC 4                    // float4
#define THREADS (EMBED / VEC)    // 256 threads cover one row per store round
#define ROWS_PER_BLOCK 4

__global__ __launch_bounds__(THREADS)
void vql_kernel(const float* __restrict__ x,
                const float* __restrict__ W,
                const float* __restrict__ b,
                float* __restrict__ out,
                int n_rows)
{
    __shared__ float s_cos[ROWS_PER_BLOCK];

    const int tid  = threadIdx.x;
    const int row0 = blockIdx.x * ROWS_PER_BLOCK;

    // Threads 0..3 compute cos(x[row,1]) for this block's rows.
    if (tid < ROWS_PER_BLOCK) {
        int r = row0 + tid;
        float v = 0.0f;
        if (r < n_rows)
            v = __ldg(&x[(size_t)r * EMBED + 1]);
        s_cos[tid] = cosf(v);
    }
    __syncthreads();

    // W/b chunk for this thread, register-resident across all 4 rows.
    const float4 w4 = __ldg(reinterpret_cast<const float4*>(W) + tid);
    const float4 b4 = __ldg(reinterpret_cast<const float4*>(b) + tid);

    float4* o = reinterpret_cast<float4*>(out) + (size_t)row0 * (EMBED / VEC) + tid;

    #pragma unroll
    for (int i = 0; i < ROWS_PER_BLOCK; ++i) {
        if (row0 + i >= n_rows) break;
        const float c = s_cos[i];
        float4 v;
        v.x = fmaf(c, w4.x, b4.x);
        v.y = fmaf(c, w4.y, b4.y);
        v.z = fmaf(c, w4.z, b4.z);
        v.w = fmaf(c, w4.w, b4.w);
        // Streaming store: output is write-once, evict-first in L2.
        __stcs(o + (size_t)i * (EMBED / VEC), v);
    }
}

extern "C" void kernel_launch(void* const* d_in, const int* in_sizes, int n_in,
                              void* d_out, int out_size)
{
    const float* x = (const float*)d_in[0];   // (32768, 1024)
    const float* W = (const float*)d_in[1];   // 1024 floats
    const float* b = (const float*)d_in[2];   // 1024 floats
    float* out = (float*)d_out;

    const int n_rows = in_sizes[0] / EMBED;                            // 32768
    const int grid = (n_rows + ROWS_PER_BLOCK - 1) / ROWS_PER_BLOCK;   // 8192

    vql_kernel<<<grid, THREADS>>>(x, W, b, out, n_rows);
}

// round 16
// speedup vs baseline: 1.0052x; 1.0052x over previous
#include <cuda_runtime.h>

// out[row, e] = cos(x[row, 1]) * W_dec[e] + b_dec[e]
// x: (32768, 1024) fp32 ; W_dec,b_dec: (1024,) ; out: (32768, 1024)
// R15: last unexplored cell in the champion family — ROWS_PER_BLOCK 4 -> 2
// (16384 blocks, ~14 waves). Halves each CTA's batched store footprint in
// the L1tex queue (reduces cross-CTA completion spread) at ~1% tail cost.
// Everything else identical to the R4 champion (smem cos broadcast,
// register-resident W/b, float4 evict-first stores).

#define EMBED 1024
#define VEC 4                    // float4
#define THREADS (EMBED / VEC)    // 256 threads cover one row per store round
#define ROWS_PER_BLOCK 2

__global__ __launch_bounds__(THREADS)
void vql_kernel(const float* __restrict__ x,
                const float* __restrict__ W,
                const float* __restrict__ b,
                float* __restrict__ out,
                int n_rows)
{
    __shared__ float s_cos[ROWS_PER_BLOCK];

    const int tid  = threadIdx.x;
    const int row0 = blockIdx.x * ROWS_PER_BLOCK;

    // Threads 0..1 compute cos(x[row,1]) for this block's rows.
    if (tid < ROWS_PER_BLOCK) {
        int r = row0 + tid;
        float v = 0.0f;
        if (r < n_rows)
            v = __ldg(&x[(size_t)r * EMBED + 1]);
        s_cos[tid] = cosf(v);
    }
    __syncthreads();

    // W/b chunk for this thread, register-resident across both rows.
    const float4 w4 = __ldg(reinterpret_cast<const float4*>(W) + tid);
    const float4 b4 = __ldg(reinterpret_cast<const float4*>(b) + tid);

    float4* o = reinterpret_cast<float4*>(out) + (size_t)row0 * (EMBED / VEC) + tid;

    #pragma unroll
    for (int i = 0; i < ROWS_PER_BLOCK; ++i) {
        if (row0 + i >= n_rows) break;
        const float c = s_cos[i];
        float4 v;
        v.x = fmaf(c, w4.x, b4.x);
        v.y = fmaf(c, w4.y, b4.y);
        v.z = fmaf(c, w4.z, b4.z);
        v.w = fmaf(c, w4.w, b4.w);
        // Streaming store: output is write-once, evict-first in L2.
        __stcs(o + (size_t)i * (EMBED / VEC), v);
    }
}

extern "C" void kernel_launch(void* const* d_in, const int* in_sizes, int n_in,
                              void* d_out, int out_size)
{
    const float* x = (const float*)d_in[0];   // (32768, 1024)
    const float* W = (const float*)d_in[1];   // 1024 floats
    const float* b = (const float*)d_in[2];   // 1024 floats
    float* out = (float*)d_out;

    const int n_rows = in_sizes[0] / EMBED;                            // 32768
    const int grid = (n_rows + ROWS_PER_BLOCK - 1) / ROWS_PER_BLOCK;   // 16384

    vql_kernel<<<grid, THREADS>>>(x, W, b, out, n_rows);
}

// round 17
// speedup vs baseline: 1.0066x; 1.0013x over previous
#include <cuda_runtime.h>

// out[row, e] = cos(x[row, 1]) * W_dec[e] + b_dec[e]
// x: (32768, 1024) fp32 ; W_dec,b_dec: (1024,) ; out: (32768, 1024)
//
// FINAL — R4 champion, byte-identical (best measured 23.42us; isolated
// kernel time stable at 23.8 +/- 0.2us across 6 runs).
// Roofline: pinned at the DRAM write ceiling, ~5.7 TB/s effective on the
// irreducible 134 MB fp32 output (71% of 8 TB/s spec). Store-issue floor
// ~11us and LTS cap both have ~2x headroom. Harness noise ~1.1us.
// Axis closure (all measured): store width v8 (+2.4us) | rows/block 8
// (+1.2us) and 2 (+4.5us isolated) | persistent grid (+3us) | wb stores
// (+5us) | hybrid wb/cs (+1.1us) | evict_last pinning (+1.2us) | TMA bulk
// store (+4.5us) | shfl broadcast (tie) | straight-line burst (+0.6us).
// Config: 8192 blocks x 256 threads, 4 rows/block (7 waves, ~1% tail),
// smem cos broadcast, register-resident W/b, float4 evict-first stores.

#define EMBED 1024
#define VEC 4                    // float4
#define THREADS (EMBED / VEC)    // 256 threads cover one row per store round
#define ROWS_PER_BLOCK 4

__global__ __launch_bounds__(THREADS)
void vql_kernel(const float* __restrict__ x,
                const float* __restrict__ W,
                const float* __restrict__ b,
                float* __restrict__ out,
                int n_rows)
{
    __shared__ float s_cos[ROWS_PER_BLOCK];

    const int tid  = threadIdx.x;
    const int row0 = blockIdx.x * ROWS_PER_BLOCK;

    // Threads 0..3 compute cos(x[row,1]) for this block's rows.
    if (tid < ROWS_PER_BLOCK) {
        int r = row0 + tid;
        float v = 0.0f;
        if (r < n_rows)
            v = __ldg(&x[(size_t)r * EMBED + 1]);
        s_cos[tid] = cosf(v);
    }
    __syncthreads();

    // W/b chunk for this thread, register-resident across all 4 rows.
    const float4 w4 = __ldg(reinterpret_cast<const float4*>(W) + tid);
    const float4 b4 = __ldg(reinterpret_cast<const float4*>(b) + tid);

    float4* o = reinterpret_cast<float4*>(out) + (size_t)row0 * (EMBED / VEC) + tid;

    #pragma unroll
    for (int i = 0; i < ROWS_PER_BLOCK; ++i) {
        if (row0 + i >= n_rows) break;
        const float c = s_cos[i];
        float4 v;
        v.x = fmaf(c, w4.x, b4.x);
        v.y = fmaf(c, w4.y, b4.y);
        v.z = fmaf(c, w4.z, b4.z);
        v.w = fmaf(c, w4.w, b4.w);
        // Streaming store: output is write-once, evict-first in L2.
        __stcs(o + (size_t)i * (EMBED / VEC), v);
    }
}

extern "C" void kernel_launch(void* const* d_in, const int* in_sizes, int n_in,
                              void* d_out, int out_size)
{
    const float* x = (const float*)d_in[0];   // (32768, 1024)
    const float* W = (const float*)d_in[1];   // 1024 floats
    const float* b = (const float*)d_in[2];   // 1024 floats
    float* out = (float*)d_out;

    const int n_rows = in_sizes[0] / EMBED;                            // 32768
    const int grid = (n_rows + ROWS_PER_BLOCK - 1) / ROWS_PER_BLOCK;   // 8192

    vql_kernel<<<grid, THREADS>>>(x, W, b, out, n_rows);
}